// round 6
// baseline (speedup 1.0000x reference)
#include <cuda_runtime.h>
#include <math.h>

// Diffusion: out = expm(-max(t,1e-8)*L) @ x, L = graph Laplacian (~32 nnz/row).
// Chebyshev expansion of e^{-t*lambda} on [0, lambda_ub] applied via fp32
// sparse matvecs in one persistent kernel (software grid barrier).
// NEW (R5): lambda_ub tightened from Gershgorin (2*d_max ~ 51) to a certified
// Collatz-Wielandt bound on the signless Laplacian Q = D+A (~ 28), cutting the
// Chebyshev degree ~20 -> ~13. Every CW iterate max_i (Qy)_i/y_i is a rigorous
// upper bound on lambda_max(Q) >= lambda_max(L), so no safety factor needed.

#define NN   2048
#define DD   512
#define ELLW 128          // max off-diag nnz per row (mean ~32)
#define MMAX 48           // highest Chebyshev degree available
#define RPB  8            // rows per block
#define TPR  64           // threads per row (8 channels each)
#define THREADS (RPB*TPR) // 512
#define GRID (NN/RPB)     // 256 blocks  (<= 148 SMs * 2 resident)

#define CWB  16           // CW kernel blocks
#define CWT  128          // CW kernel threads/block  -> 2048 = one row each
#define CWI  8            // Collatz-Wielandt iterations

// -------- device-global scratch (no allocations allowed) --------
__device__ int   g_cnt[NN];
__device__ float g_diag[NN];
__device__ int   g_col[NN * ELLW];
__device__ float g_val[NN * ELLW];
__device__ float g_coef[MMAX + 1];
__device__ float g_a;     // 4 / lambda_ub
__device__ int   g_deg;   // truncation degree (data dependent)
__device__ float g_T1[NN * DD];
__device__ float g_T2[NN * DD];
__device__ float g_y[2][NN];         // CW power vector (ping-pong)
__device__ int   g_cw_bound[CWI];    // per-iter CW bound, float bits (>=0)

// software grid barrier state (persist kernel)
__device__ int          g_bar_count = 0;
__device__ volatile int g_bar_gen   = 0;
// separate barrier for the CW kernel
__device__ int          g_bar2_count = 0;
__device__ volatile int g_bar2_gen   = 0;

__device__ __forceinline__ float4 f4_load(const float* p) {
    return *reinterpret_cast<const float4*>(p);
}
__device__ __forceinline__ void f4_store(float* p, float4 v) {
    *reinterpret_cast<float4*>(p) = v;
}

template <int NBLK>
__device__ __forceinline__ void grid_barrier_impl(int* cnt, volatile int* gen) {
    __threadfence();
    __syncthreads();
    if (threadIdx.x == 0) {
        int g = *gen;
        if (atomicAdd(cnt, 1) == NBLK - 1) {
            *cnt = 0;
            __threadfence();
            *gen = g + 1;
        } else {
            while (*gen == g) __nanosleep(64);
        }
        __threadfence();
    }
    __syncthreads();
}

// ---------------------------------------------------------------------------
// 1) Extract sparse structure from dense L (one block per row).
// ---------------------------------------------------------------------------
__global__ void __launch_bounds__(256) prep_kernel(const float* __restrict__ L) {
    int row = blockIdx.x;
    int t   = threadIdx.x;
    const float* Lr = L + (size_t)row * NN;

    int   cols[8];
    float vals[8];
    int   cnt  = 0;
    float dval = 0.f;
    int base = t * 8;
#pragma unroll
    for (int k = 0; k < 8; k++) {
        int c = base + k;
        float v = Lr[c];
        if (c == row) {
            dval = v;
        } else if (v != 0.f) {
            cols[cnt] = c;
            vals[cnt] = -v;   // A_ij = -L_ij
            cnt++;
        }
    }

    __shared__ int s_scan[256];
    s_scan[t] = cnt;
    __syncthreads();
    for (int off = 1; off < 256; off <<= 1) {
        int add = (t >= off) ? s_scan[t - off] : 0;
        __syncthreads();
        s_scan[t] += add;
        __syncthreads();
    }
    int offset = s_scan[t] - cnt;
    int total  = s_scan[255];

    for (int k = 0; k < cnt; k++) {
        int idx = offset + k;
        if (idx < ELLW) {
            g_col[row * ELLW + idx] = cols[k];
            g_val[row * ELLW + idx] = vals[k];
        }
    }
    if ((row >> 3) == t) g_diag[row] = dval;
    if (t == 0) g_cnt[row] = (total < ELLW) ? total : ELLW;
}

// ---------------------------------------------------------------------------
// 2) Spectral bound + Chebyshev coefficients, one cooperative kernel.
//    Phase A: CWI Collatz-Wielandt iterations on Q = D + A give a certified
//             lambda_ub (running min with Gershgorin 2*d_max).
//    Phase B: block 0, warp 0: 64-node fp64 DCT of exp(-z*(s+1)),
//             truncation degree with tail tolerance 2e-5.
// ---------------------------------------------------------------------------
__global__ void __launch_bounds__(CWT) cw_coeff_kernel(const float* __restrict__ t_in) {
    const int row = blockIdx.x * CWT + threadIdx.x;   // 0..2047, one per row

    // reset bound slots (fresh every graph replay) and init y0 = d + 1 > 0
    if (blockIdx.x == 0 && threadIdx.x < CWI) g_cw_bound[threadIdx.x] = 0;
    const float d = g_diag[row];
    g_y[0][row] = d + 1.0f;

    const int cnt = g_cnt[row];
    // keep this row's list in registers? cnt variable; just gather from L2.

    grid_barrier_impl<CWB>(&g_bar2_count, &g_bar2_gen);

    for (int it = 0; it < CWI; it++) {
        const float* y = g_y[it & 1];
        float yr = y[row];
        float q = d * yr;
        const int*   sc = g_col + row * ELLW;
        const float* sv = g_val + row * ELLW;
        for (int k = 0; k < cnt; k++)
            q += sv[k] * y[sc[k]];           // Q = D + A (weights positive)
        float ratio = (yr > 1e-30f) ? (q / yr) : 0.0f;
        // rounding guard: a 32-term fp32 sum is accurate to ~1e-6 rel
        ratio *= 1.00001f;
        atomicMax(&g_cw_bound[it], __float_as_int(ratio));  // ratio >= 0
        g_y[(it + 1) & 1][row] = q;
        grid_barrier_impl<CWB>(&g_bar2_count, &g_bar2_gen);
    }

    if (blockIdx.x != 0 || threadIdx.x >= 32) return;
    const int lane = threadIdx.x;

    // Gershgorin: 2 * max weighted degree
    float m = 0.f;
    for (int i = lane; i < NN; i += 32) m = fmaxf(m, g_diag[i]);
#pragma unroll
    for (int off = 16; off; off >>= 1)
        m = fmaxf(m, __shfl_xor_sync(0xffffffffu, m, off));
    double lub = 2.0 * (double)m;

    // running min with every CW iterate (each independently valid)
    for (int it = 0; it < CWI; it++) {
        double b = (double)__int_as_float(g_cw_bound[it]);
        if (b > 1e-12 && b < lub) lub = b;
    }
    if (lub < 1e-12) lub = 1e-12;

    double tt = (double)fmaxf(t_in[0], 1e-8f);
    double z  = 0.5 * tt * lub;

    const double PI = 3.14159265358979323846;
    double th0 = PI * ((double)lane + 0.5) / 64.0;
    double th1 = PI * ((double)(lane + 32) + 0.5) / 64.0;
    double ct0 = cos(th0), ct1 = cos(th1);
    double f0 = exp(-z * (ct0 + 1.0));
    double f1 = exp(-z * (ct1 + 1.0));

    double cm2_0 = 1.0, cm1_0 = ct0, tc0 = 2.0 * ct0;
    double cm2_1 = 1.0, cm1_1 = ct1, tc1 = 2.0 * ct1;

    __shared__ double s_c[MMAX + 1];
    for (int k = 0; k <= MMAX; k++) {
        double ck0, ck1;
        if (k == 0)      { ck0 = 1.0; ck1 = 1.0; }
        else if (k == 1) { ck0 = ct0; ck1 = ct1; }
        else {
            ck0 = tc0 * cm1_0 - cm2_0;  cm2_0 = cm1_0;  cm1_0 = ck0;
            ck1 = tc1 * cm1_1 - cm2_1;  cm2_1 = cm1_1;  cm1_1 = ck1;
        }
        double p = f0 * ck0 + f1 * ck1;
#pragma unroll
        for (int off = 16; off; off >>= 1)
            p += __shfl_xor_sync(0xffffffffu, p, off);
        if (lane == 0) {
            double c = (2.0 / 64.0) * p;
            if (k == 0) c *= 0.5;
            s_c[k] = c;
        }
    }
    __syncwarp();
    if (lane == 0) {
        double tail = 0.0;
        int deg = 2;
        for (int k = MMAX; k >= 2; k--) {
            tail += fabs(s_c[k]);
            if (tail > 2e-5) { deg = k; break; }
        }
        if (deg > MMAX) deg = MMAX;
        g_deg = deg;
        g_a   = (float)(4.0 / lub);
        for (int k = 0; k <= MMAX; k++) g_coef[k] = (float)s_c[k];
    }
}

// ---------------------------------------------------------------------------
// SpMV core: acc[0..7] = d*yk - sum_j val_j * Y[col_j, ch..ch+7]
// ---------------------------------------------------------------------------
__device__ __forceinline__ void spmv8(const float* __restrict__ Y, int ch,
                                      const int* __restrict__ sc,
                                      const float* __restrict__ sv,
                                      int cnt, float d,
                                      const float yk[8], float acc[8]) {
#pragma unroll
    for (int i = 0; i < 8; i++) acc[i] = d * yk[i];
    int k = 0;
    for (; k + 2 <= cnt; k += 2) {
        int   c0 = sc[k],     c1 = sc[k + 1];
        float v0 = sv[k],     v1 = sv[k + 1];
        const float* p0 = Y + (((size_t)c0) << 9) + ch;
        const float* p1 = Y + (((size_t)c1) << 9) + ch;
        float4 a0 = f4_load(p0), a1 = f4_load(p0 + 4);
        float4 b0 = f4_load(p1), b1 = f4_load(p1 + 4);
        acc[0] -= v0 * a0.x; acc[1] -= v0 * a0.y; acc[2] -= v0 * a0.z; acc[3] -= v0 * a0.w;
        acc[4] -= v0 * a1.x; acc[5] -= v0 * a1.y; acc[6] -= v0 * a1.z; acc[7] -= v0 * a1.w;
        acc[0] -= v1 * b0.x; acc[1] -= v1 * b0.y; acc[2] -= v1 * b0.z; acc[3] -= v1 * b0.w;
        acc[4] -= v1 * b1.x; acc[5] -= v1 * b1.y; acc[6] -= v1 * b1.z; acc[7] -= v1 * b1.w;
    }
    if (k < cnt) {
        int   c0 = sc[k];
        float v0 = sv[k];
        const float* p0 = Y + (((size_t)c0) << 9) + ch;
        float4 a0 = f4_load(p0), a1 = f4_load(p0 + 4);
        acc[0] -= v0 * a0.x; acc[1] -= v0 * a0.y; acc[2] -= v0 * a0.z; acc[3] -= v0 * a0.w;
        acc[4] -= v0 * a1.x; acc[5] -= v0 * a1.y; acc[6] -= v0 * a1.z; acc[7] -= v0 * a1.w;
    }
}

// ---------------------------------------------------------------------------
// 3) Persistent Chebyshev kernel: all iterations, grid barrier between them.
// ---------------------------------------------------------------------------
__global__ void __launch_bounds__(THREADS, 2)
cheb_persist(const float* __restrict__ X, float* __restrict__ out) {
    const int rl   = threadIdx.x >> 6;       // row within block (0..7)
    const int lane = threadIdx.x & 63;
    const int row  = blockIdx.x * RPB + rl;

    __shared__ int   s_col[RPB][ELLW];
    __shared__ float s_val[RPB][ELLW];
    __shared__ float s_ykm1[RPB][TPR * 8];
    __shared__ float s_coef[MMAX + 1];

    const int cnt = g_cnt[row];
    for (int k = lane; k < cnt; k += TPR) {
        s_col[rl][k] = g_col[row * ELLW + k];
        s_val[rl][k] = g_val[row * ELLW + k];
    }
    if (threadIdx.x <= MMAX) s_coef[threadIdx.x] = g_coef[threadIdx.x];
    __syncthreads();

    const float d   = g_diag[row];
    const float a   = g_a;        // 4/lub
    const int   deg = g_deg;
    const int   ch  = lane << 3;
    const size_t ridx = (((size_t)row) << 9) + ch;

    float yk[8], acc[8], o[8];
    {
        float4 xa = f4_load(X + ridx), xb = f4_load(X + ridx + 4);
        yk[0] = xa.x; yk[1] = xa.y; yk[2] = xa.z; yk[3] = xa.w;
        yk[4] = xb.x; yk[5] = xb.y; yk[6] = xb.z; yk[7] = xb.w;
    }

    // T1 = (2/lub)*L@x - x ;  out = c0*x + c1*T1
    spmv8(X, ch, s_col[rl], s_val[rl], cnt, d, yk, acc);
    {
        const float ha = 0.5f * a;
        const float c0 = s_coef[0], c1 = s_coef[1];
#pragma unroll
        for (int i = 0; i < 8; i++) {
            float t1 = ha * acc[i] - yk[i];
            o[i] = c0 * yk[i] + c1 * t1;
            s_ykm1[rl][ch + i] = yk[i];   // T0
            yk[i] = t1;                   // T1
        }
        float4 va = {yk[0], yk[1], yk[2], yk[3]};
        float4 vb = {yk[4], yk[5], yk[6], yk[7]};
        f4_store(g_T1 + ridx, va);
        f4_store(g_T1 + ridx + 4, vb);
    }

    for (int j = 2; j <= deg; j++) {
        grid_barrier_impl<GRID>(&g_bar_count, &g_bar_gen);
        const float* Tp = (j & 1) ? g_T2 : g_T1;
        float*       Tc = (j & 1) ? g_T1 : g_T2;

        spmv8(Tp, ch, s_col[rl], s_val[rl], cnt, d, yk, acc);

        const float c = s_coef[j];
        float tn[8];
#pragma unroll
        for (int i = 0; i < 8; i++) {
            tn[i] = a * acc[i] - 2.f * yk[i] - s_ykm1[rl][ch + i];
            o[i] += c * tn[i];
            s_ykm1[rl][ch + i] = yk[i];
            yk[i] = tn[i];
        }
        if (j < deg) {                        // last T never gathered
            float4 va = {tn[0], tn[1], tn[2], tn[3]};
            float4 vb = {tn[4], tn[5], tn[6], tn[7]};
            f4_store(Tc + ridx, va);
            f4_store(Tc + ridx + 4, vb);
        }
    }

    float4 oa = {o[0], o[1], o[2], o[3]};
    float4 ob = {o[4], o[5], o[6], o[7]};
    f4_store(out + ridx, oa);
    f4_store(out + ridx + 4, ob);
}

// ---------------------------------------------------------------------------
extern "C" void kernel_launch(void* const* d_in, const int* in_sizes, int n_in,
                              void* d_out, int out_size) {
    const float* x = nullptr;
    const float* L = nullptr;
    const float* t = nullptr;
    for (int i = 0; i < n_in; i++) {
        if      (in_sizes[i] == NN * DD) x = (const float*)d_in[i];
        else if (in_sizes[i] == NN * NN) L = (const float*)d_in[i];
        else if (in_sizes[i] == 1)       t = (const float*)d_in[i];
    }
    float* out = (float*)d_out;

    prep_kernel<<<NN, 256>>>(L);
    cw_coeff_kernel<<<CWB, CWT>>>(t);
    cheb_persist<<<GRID, THREADS>>>(x, out);
}